// round 7
// baseline (speedup 1.0000x reference)
#include <cuda_runtime.h>

// GatedDeltaRuleModule: 5-tap causal local attention, memory-bound.
// B=2, S=8192, H=16, D=128, W=4.
// out[b,s,h,:] = sum_{d=0..4} (q_s . k_{s-d}) * scale * sigmoid(a_s * b_{s-d}) * v_{s-d}
// out[b,0,h,:] = v[b,0,h,:]
//
// R5 change vs R4: 8-lane dot reduction (lane = 4 rows x 8 sub-lanes, 16 cols/sub)
// cuts warp SHFL count 800 -> 120 per block to unclog the MIO/L1 pipe (was 75.2%).

#define BATCH 2
#define SEQ   8192
#define HEADS 16
#define DIM   128
#define WIN   4
#define TILE  32
#define THREADS 256
#define HALO_ROWS (TILE + WIN)

__global__ __launch_bounds__(THREADS, 5)
void gdr_local_attn_kernel(const float* __restrict__ q,
                           const float* __restrict__ k,
                           const float* __restrict__ v,
                           const float* __restrict__ a,
                           const float* __restrict__ b,
                           float* __restrict__ out)
{
    // k/v tiles with WIN-row halo on the left. Row r <-> global s = s0 - WIN + r.
    __shared__ float ks[HALO_ROWS * DIM];
    __shared__ float vs[HALO_ROWS * DIM];
    __shared__ float bsh[HALO_ROWS];
    __shared__ float ash[TILE];

    const int s0  = blockIdx.x * TILE;
    const int h   = blockIdx.y;
    const int bb  = blockIdx.z;
    const int tid = threadIdx.x;

    const float SCALE = 0.08838834764831845f;  // 1/sqrt(128)

    // ---- Cooperative tile load (float4, fully coalesced) ----
    for (int idx = tid; idx < HALO_ROWS * (DIM / 4); idx += THREADS) {
        const int r  = idx >> 5;         // DIM/4 = 32 float4 per row
        const int c4 = idx & 31;
        const int s  = s0 - WIN + r;
        float4 kk = make_float4(0.f, 0.f, 0.f, 0.f);
        float4 vv = kk;
        if (s >= 0) {
            const size_t base = ((((size_t)bb * SEQ + s) * HEADS) + h) * DIM + c4 * 4;
            kk = *reinterpret_cast<const float4*>(k + base);
            vv = *reinterpret_cast<const float4*>(v + base);
        }
        *reinterpret_cast<float4*>(ks + r * DIM + c4 * 4) = kk;
        *reinterpret_cast<float4*>(vs + r * DIM + c4 * 4) = vv;
    }
    for (int idx = tid; idx < HALO_ROWS; idx += THREADS) {
        const int s = s0 - WIN + idx;
        bsh[idx] = (s >= 0) ? b[((size_t)bb * SEQ + s) * HEADS + h] : 0.f;
        if (idx < TILE)
            ash[idx] = a[((size_t)bb * SEQ + s0 + idx) * HEADS + h];
    }
    __syncthreads();

    const int warp = tid >> 5;
    const int lane = tid & 31;
    const int g    = lane >> 3;   // which of this warp's 4 rows (processed concurrently)
    const int sub  = lane & 7;    // 8-lane sub-group position within the row

    // Warp w owns rows w*4 .. w*4+3; one straight-line pass, no row loop.
    const int i   = warp * 4 + g;         // 0..31
    const int s   = s0 + i;
    const int r_s = i + WIN;              // smem row of position s
    const size_t rowbase = ((((size_t)bb * SEQ + s) * HEADS) + h) * (size_t)DIM;

    // sub owns 16 columns: float4 chunks {sub, sub+8, sub+16, sub+24}.
    // Smem bank pattern per quarter-warp phase: banks sub*4..sub*4+3 -> conflict-free.
    float4 q4[4];
#pragma unroll
    for (int p = 0; p < 4; p++)
        q4[p] = *reinterpret_cast<const float4*>(q + rowbase + (sub + p * 8) * 4);

    // 5 per-lane dot partials over 16 columns each
    float part[WIN + 1];
#pragma unroll
    for (int d = 0; d <= WIN; d++) {
        const float* kr = ks + (r_s - d) * DIM;
        float sum = 0.f;
#pragma unroll
        for (int p = 0; p < 4; p++) {
            const float4 k4 = *reinterpret_cast<const float4*>(kr + (sub + p * 8) * 4);
            sum += q4[p].x * k4.x + q4[p].y * k4.y + q4[p].z * k4.z + q4[p].w * k4.w;
        }
        part[d] = sum;
    }
    // 3-step butterfly within the 8-lane sub-group (xor masks stay inside the group).
    // Batched over the 5 taps for ILP: 15 SHFLs per warp total.
#pragma unroll
    for (int off = 4; off > 0; off >>= 1) {
#pragma unroll
        for (int d = 0; d <= WIN; d++)
            part[d] += __shfl_xor_sync(0xffffffffu, part[d], off);
    }

    const float av = ash[i];
    float4 acc[4];
#pragma unroll
    for (int p = 0; p < 4; p++) acc[p] = make_float4(0.f, 0.f, 0.f, 0.f);

#pragma unroll
    for (int d = 0; d <= WIN; d++) {
        // Halo rows (s-d < 0) were zero-filled: part==0 and v==0, matching the
        // reference's zero-padding exactly. No boundary branch.
        const float gate  = 1.0f / (1.0f + __expf(-av * bsh[r_s - d]));
        const float coeff = part[d] * SCALE * gate;
        const float* vr = vs + (r_s - d) * DIM;
#pragma unroll
        for (int p = 0; p < 4; p++) {
            const float4 v4 = *reinterpret_cast<const float4*>(vr + (sub + p * 8) * 4);
            acc[p].x += coeff * v4.x;
            acc[p].y += coeff * v4.y;
            acc[p].z += coeff * v4.z;
            acc[p].w += coeff * v4.w;
        }
    }

    if (s == 0) {  // reference special-cases position 0: out = v_0
#pragma unroll
        for (int p = 0; p < 4; p++)
            acc[p] = *reinterpret_cast<const float4*>(vs + WIN * DIM + (sub + p * 8) * 4);
    }

#pragma unroll
    for (int p = 0; p < 4; p++)
        *reinterpret_cast<float4*>(out + rowbase + (sub + p * 8) * 4) = acc[p];
}

extern "C" void kernel_launch(void* const* d_in, const int* in_sizes, int n_in,
                              void* d_out, int out_size)
{
    const float* q = (const float*)d_in[0];
    const float* k = (const float*)d_in[1];
    const float* v = (const float*)d_in[2];
    const float* a = (const float*)d_in[3];
    const float* b = (const float*)d_in[4];
    float* out = (float*)d_out;

    dim3 grid(SEQ / TILE, HEADS, BATCH);  // (256, 16, 2) = 8192 blocks
    gdr_local_attn_kernel<<<grid, THREADS>>>(q, k, v, a, b, out);
}

// round 9
// speedup vs baseline: 1.1060x; 1.1060x over previous
#include <cuda_runtime.h>

// GatedDeltaRuleModule: 5-tap causal local attention. B=2, S=8192, H=16, D=128, W=4.
// out[b,s,h,:] = sum_{d=0..4} (q_s . k_{s-d}) * scale * sigmoid(a_s * b_{s-d}) * v_{s-d}
// out[b,0,h,:] = v[b,0,h,:]
//
// R7: register-streaming design. One warp owns a contiguous 64-row strip of one
// (batch, head). The W=4 causal history of k/v/b lives in a rolling register
// window (4 x float4 per lane). No shared memory, no barriers, no halo re-reads:
// k,v,q read exactly once (537 MB floor), out written once. 4096 warps resident
// in a single wave; aggregate LDG concurrency saturates HBM even with per-warp
// latency fully exposed.

#define BATCH 2
#define SEQ   8192
#define HEADS 16
#define DIM   128
#define CH    64                    // rows per warp strip
#define THREADS 256
#define CHUNKS (SEQ / CH)           // 128
#define WARPS_PER_BLOCK (THREADS / 32)
#define TOTAL_WARPS (BATCH * HEADS * CHUNKS)   // 4096
#define NBLOCKS (TOTAL_WARPS / WARPS_PER_BLOCK) // 512

__device__ __forceinline__ float dot4(const float4 a, const float4 b) {
    return a.x * b.x + a.y * b.y + a.z * b.z + a.w * b.w;
}

__global__ __launch_bounds__(THREADS, 4)
void gdr_stream_kernel(const float* __restrict__ q,
                       const float* __restrict__ k,
                       const float* __restrict__ v,
                       const float* __restrict__ a,
                       const float* __restrict__ b,
                       float* __restrict__ out)
{
    const int lane = threadIdx.x & 31;
    const int wg   = blockIdx.x * WARPS_PER_BLOCK + (threadIdx.x >> 5);

    const int chunk = wg & (CHUNKS - 1);          // bits 0..6
    const int h     = (wg >> 7) & (HEADS - 1);    // bits 7..10
    const int bb    = wg >> 11;                   // bit 11
    const int s0    = chunk * CH;

    const float  SCALE     = 0.08838834764831845f;   // 1/sqrt(128)
    const size_t ROWSTRIDE = (size_t)HEADS * DIM;    // 2048 floats = 8 KB

    // Offset of row s0 for q/k/v/out (identical layout): lane owns 16B at lane*4.
    size_t off = (((size_t)bb * SEQ + s0) * HEADS + h) * DIM + (size_t)(lane * 4);
    int    ab  = (bb * SEQ + s0) * HEADS + h;        // a/b index, stride HEADS per row

    // ---- Rolling history window: rows s-1..s-4 (zero for s<0, matching padding) ----
    const float4 z4 = make_float4(0.f, 0.f, 0.f, 0.f);
    float4 k1 = z4, k2 = z4, k3 = z4, k4 = z4;
    float4 v1 = z4, v2 = z4, v3 = z4, v4 = z4;
    float  b1 = 0.f, b2 = 0.f, b3 = 0.f, b4 = 0.f;

    if (s0 >= 1) {
        k1 = *reinterpret_cast<const float4*>(k + off - 1 * ROWSTRIDE);
        v1 = *reinterpret_cast<const float4*>(v + off - 1 * ROWSTRIDE);
        b1 = b[ab - 1 * HEADS];
        // s0 is a multiple of CH=64, so s0>=1 implies s0>=64 and all 4 halo rows exist.
        k2 = *reinterpret_cast<const float4*>(k + off - 2 * ROWSTRIDE);
        v2 = *reinterpret_cast<const float4*>(v + off - 2 * ROWSTRIDE);
        b2 = b[ab - 2 * HEADS];
        k3 = *reinterpret_cast<const float4*>(k + off - 3 * ROWSTRIDE);
        v3 = *reinterpret_cast<const float4*>(v + off - 3 * ROWSTRIDE);
        b3 = b[ab - 3 * HEADS];
        k4 = *reinterpret_cast<const float4*>(k + off - 4 * ROWSTRIDE);
        v4 = *reinterpret_cast<const float4*>(v + off - 4 * ROWSTRIDE);
        b4 = b[ab - 4 * HEADS];
    }

    const bool first_chunk = (s0 == 0);

#pragma unroll 4
    for (int i = 0; i < CH; ++i) {
        // Current-row loads. v is consumed late (good natural latency distance);
        // q/k feed the dot immediately — exposure is covered by 27 warps/SM.
        const float4 cq = *reinterpret_cast<const float4*>(q + off);
        const float4 ck = *reinterpret_cast<const float4*>(k + off);
        const float4 cv = *reinterpret_cast<const float4*>(v + off);
        const float  ca = a[ab];
        const float  cb = b[ab];

        // 5 per-lane dot partials over this lane's 4 columns.
        float p0 = dot4(cq, ck);
        float p1 = dot4(cq, k1);
        float p2 = dot4(cq, k2);
        float p3 = dot4(cq, k3);
        float p4 = dot4(cq, k4);

        // Full-warp butterfly reduction, 5 taps interleaved for ILP (25 SHFL).
#pragma unroll
        for (int offx = 16; offx > 0; offx >>= 1) {
            p0 += __shfl_xor_sync(0xffffffffu, p0, offx);
            p1 += __shfl_xor_sync(0xffffffffu, p1, offx);
            p2 += __shfl_xor_sync(0xffffffffu, p2, offx);
            p3 += __shfl_xor_sync(0xffffffffu, p3, offx);
            p4 += __shfl_xor_sync(0xffffffffu, p4, offx);
        }

        // Gates. Halo rows (s-d<0) were zero-filled: p==0 -> contribution 0,
        // exactly matching the reference's zero-padding.
        const float c0 = p0 * SCALE * (1.0f / (1.0f + __expf(-ca * cb)));
        const float c1 = p1 * SCALE * (1.0f / (1.0f + __expf(-ca * b1)));
        const float c2 = p2 * SCALE * (1.0f / (1.0f + __expf(-ca * b2)));
        const float c3 = p3 * SCALE * (1.0f / (1.0f + __expf(-ca * b3)));
        const float c4 = p4 * SCALE * (1.0f / (1.0f + __expf(-ca * b4)));

        float4 acc;
        acc.x = c0 * cv.x + c1 * v1.x + c2 * v2.x + c3 * v3.x + c4 * v4.x;
        acc.y = c0 * cv.y + c1 * v1.y + c2 * v2.y + c3 * v3.y + c4 * v4.y;
        acc.z = c0 * cv.z + c1 * v1.z + c2 * v2.z + c3 * v3.z + c4 * v4.z;
        acc.w = c0 * cv.w + c1 * v1.w + c2 * v2.w + c3 * v3.w + c4 * v4.w;

        if (first_chunk && i == 0)   // reference special-cases s==0: out = v_0
            acc = cv;

        *reinterpret_cast<float4*>(out + off) = acc;

        // Slide the window (register renaming under unroll; residual MOVs are cheap ALU).
        k4 = k3; k3 = k2; k2 = k1; k1 = ck;
        v4 = v3; v3 = v2; v2 = v1; v1 = cv;
        b4 = b3; b3 = b2; b2 = b1; b1 = cb;

        off += ROWSTRIDE;
        ab  += HEADS;
    }
}

extern "C" void kernel_launch(void* const* d_in, const int* in_sizes, int n_in,
                              void* d_out, int out_size)
{
    const float* q = (const float*)d_in[0];
    const float* k = (const float*)d_in[1];
    const float* v = (const float*)d_in[2];
    const float* a = (const float*)d_in[3];
    const float* b = (const float*)d_in[4];
    float* out = (float*)d_out;

    gdr_stream_kernel<<<NBLOCKS, THREADS>>>(q, k, v, a, b, out);
}

// round 10
// speedup vs baseline: 1.3085x; 1.1831x over previous
#include <cuda_runtime.h>
#include <cstdint>

// GatedDeltaRuleModule: 5-tap causal local attention. B=2, S=8192, H=16, D=128, W=4.
// out[b,s,h,:] = sum_{d=0..4} (q_s . k_{s-d}) * scale * sigmoid(a_s * b_{s-d}) * v_{s-d}
// out[b,0,h,:] = v[b,0,h,:]
//
// R9: warp-strip streaming (k/v history in a rolling register window) + per-warp
// cp.async smem ring staging q/k/v 3 rows ahead. Bytes-in-flight decoupled from
// registers: ~4.6 KB/warp * ~28 warps/SM ≈ 130 KB/SM >> latency-BW product, so
// DRAM latency is absorbed by pipeline depth, not occupancy. 128-thread blocks
// (1024 total) give single-wave residency at 8-block/SM caps. No block barriers;
// one __syncwarp total.

#define BATCH 2
#define SEQ   8192
#define HEADS 16
#define DIM   128
#define WIN   4
#define CH    64
#define THREADS 128
#define WPB   4
#define CHUNKS (SEQ / CH)                       // 128
#define NBLOCKS (BATCH * HEADS * CHUNKS / WPB)  // 1024
#define NSLOT 4
#define PIPE  3                                 // cp.async groups in flight
#define SLOT_FLOATS (3 * DIM)                   // q|k|v row = 1536 B

struct WarpSmem {
    float ring[NSLOT][SLOT_FLOATS];  // [0..127]=q, [128..255]=k, [256..383]=v
    float ash[CH];
    float bsh[CH + WIN];             // bsh[j] = b[s0-4+j]
};

__device__ __forceinline__ float dot4(const float4 a, const float4 b) {
    return a.x * b.x + a.y * b.y + a.z * b.z + a.w * b.w;
}

__device__ __forceinline__ void cp16(uint32_t saddr, const float* g) {
    asm volatile("cp.async.cg.shared.global [%0], [%1], 16;" :: "r"(saddr), "l"(g));
}

__global__ __launch_bounds__(THREADS, 8)
void gdr_pipe_kernel(const float* __restrict__ q,
                     const float* __restrict__ k,
                     const float* __restrict__ v,
                     const float* __restrict__ a,
                     const float* __restrict__ b,
                     float* __restrict__ out)
{
    __shared__ WarpSmem wsm[WPB];

    const int lane = threadIdx.x & 31;
    const int wid  = threadIdx.x >> 5;
    const int wg   = blockIdx.x * WPB + wid;

    const int chunk = wg & (CHUNKS - 1);
    const int h     = (wg >> 7) & (HEADS - 1);
    const int bb    = wg >> 11;
    const int s0    = chunk * CH;

    const float  SCALE     = 0.08838834764831845f;  // 1/sqrt(128)
    const size_t ROWSTRIDE = (size_t)HEADS * DIM;   // 2048 floats

    WarpSmem& S = wsm[wid];
    const size_t off0 = (((size_t)bb * SEQ + s0) * HEADS + h) * DIM;
    const float* qp = q + off0 + lane * 4;
    const float* kp = k + off0 + lane * 4;
    const float* vp = v + off0 + lane * 4;
    float*       op = out + off0 + lane * 4;
    const uint32_t ring0 =
        (uint32_t)__cvta_generic_to_shared(&S.ring[0][0]) + (uint32_t)(lane * 16);

    // ---- a/b strip preload into warp-private smem (gate path off DRAM latency) ----
    for (int j = lane; j < CH + WIN; j += 32) {
        const int s = s0 - WIN + j;
        S.bsh[j] = (s >= 0) ? b[((size_t)bb * SEQ + s) * HEADS + h] : 0.f;
    }
    for (int j = lane; j < CH; j += 32)
        S.ash[j] = a[((size_t)bb * SEQ + (s0 + j)) * HEADS + h];

    // ---- k/v halo window (rows s0-1..s0-4); zero for s0==0, matching padding ----
    const float4 z4 = make_float4(0.f, 0.f, 0.f, 0.f);
    float4 k1 = z4, k2 = z4, k3 = z4, k4 = z4;
    float4 v1 = z4, v2 = z4, v3 = z4, v4 = z4;
    if (s0 != 0) {  // s0 multiple of 64 => all 4 halo rows exist
        k1 = *reinterpret_cast<const float4*>(kp - 1 * ROWSTRIDE);
        v1 = *reinterpret_cast<const float4*>(vp - 1 * ROWSTRIDE);
        k2 = *reinterpret_cast<const float4*>(kp - 2 * ROWSTRIDE);
        v2 = *reinterpret_cast<const float4*>(vp - 2 * ROWSTRIDE);
        k3 = *reinterpret_cast<const float4*>(kp - 3 * ROWSTRIDE);
        v3 = *reinterpret_cast<const float4*>(vp - 3 * ROWSTRIDE);
        k4 = *reinterpret_cast<const float4*>(kp - 4 * ROWSTRIDE);
        v4 = *reinterpret_cast<const float4*>(vp - 4 * ROWSTRIDE);
    }

    __syncwarp();  // cross-lane reads of ash/bsh in the loop

    // ---- Pipeline prologue: stage rows 0..PIPE-1 (one commit group per row) ----
#pragma unroll
    for (int i = 0; i < PIPE; i++) {
        const uint32_t dst = ring0 + (uint32_t)((i & (NSLOT - 1)) * SLOT_FLOATS * 4);
        cp16(dst,               qp + (size_t)i * ROWSTRIDE);
        cp16(dst + DIM * 4,     kp + (size_t)i * ROWSTRIDE);
        cp16(dst + 2 * DIM * 4, vp + (size_t)i * ROWSTRIDE);
        asm volatile("cp.async.commit_group;" ::: "memory");
    }

    const bool first_chunk = (s0 == 0);

    for (int i = 0; i < CH; ++i) {
        // Completed groups >= (PIPE + i) - 2 = i+1  ->  row i's data has landed.
        asm volatile("cp.async.wait_group 2;" ::: "memory");

        const int slot = i & (NSLOT - 1);
        // Each lane reads exactly the 16B it staged itself: no syncwarp needed.
        const float4 cq = *reinterpret_cast<const float4*>(&S.ring[slot][lane * 4]);
        const float4 ck = *reinterpret_cast<const float4*>(&S.ring[slot][DIM + lane * 4]);
        const float4 cv = *reinterpret_cast<const float4*>(&S.ring[slot][2 * DIM + lane * 4]);

        // Stage row i+PIPE into slot (i+3)&3 == (i-1)&3 — consumed last iteration,
        // its LDS long retired: no smem write-after-read hazard.
        if (i + PIPE < CH) {
            const uint32_t dst =
                ring0 + (uint32_t)(((i + PIPE) & (NSLOT - 1)) * SLOT_FLOATS * 4);
            cp16(dst,               qp + (size_t)(i + PIPE) * ROWSTRIDE);
            cp16(dst + DIM * 4,     kp + (size_t)(i + PIPE) * ROWSTRIDE);
            cp16(dst + 2 * DIM * 4, vp + (size_t)(i + PIPE) * ROWSTRIDE);
        }
        asm volatile("cp.async.commit_group;" ::: "memory");  // keep group count uniform

        // 5 per-lane dot partials
        float p0 = dot4(cq, ck);
        float p1 = dot4(cq, k1);
        float p2 = dot4(cq, k2);
        float p3 = dot4(cq, k3);
        float p4 = dot4(cq, k4);

        // Full-warp butterfly, 5 taps interleaved (25 SHFL)
#pragma unroll
        for (int offx = 16; offx > 0; offx >>= 1) {
            p0 += __shfl_xor_sync(0xffffffffu, p0, offx);
            p1 += __shfl_xor_sync(0xffffffffu, p1, offx);
            p2 += __shfl_xor_sync(0xffffffffu, p2, offx);
            p3 += __shfl_xor_sync(0xffffffffu, p3, offx);
            p4 += __shfl_xor_sync(0xffffffffu, p4, offx);
        }

        // Gates from smem (LDS broadcast). bsh[i+4-d] = b[s-d]; halo rows are
        // zero-filled so p==0 there, matching the reference's zero-padding.
        const float ca = S.ash[i];
        const float c0 = p0 * SCALE * (1.0f / (1.0f + __expf(-ca * S.bsh[i + 4])));
        const float c1 = p1 * SCALE * (1.0f / (1.0f + __expf(-ca * S.bsh[i + 3])));
        const float c2 = p2 * SCALE * (1.0f / (1.0f + __expf(-ca * S.bsh[i + 2])));
        const float c3 = p3 * SCALE * (1.0f / (1.0f + __expf(-ca * S.bsh[i + 1])));
        const float c4 = p4 * SCALE * (1.0f / (1.0f + __expf(-ca * S.bsh[i + 0])));

        float4 acc;
        acc.x = c0 * cv.x + c1 * v1.x + c2 * v2.x + c3 * v3.x + c4 * v4.x;
        acc.y = c0 * cv.y + c1 * v1.y + c2 * v2.y + c3 * v3.y + c4 * v4.y;
        acc.z = c0 * cv.z + c1 * v1.z + c2 * v2.z + c3 * v3.z + c4 * v4.z;
        acc.w = c0 * cv.w + c1 * v1.w + c2 * v2.w + c3 * v3.w + c4 * v4.w;

        if (first_chunk && i == 0)  // reference special-cases s==0: out = v_0
            acc = cv;

        *reinterpret_cast<float4*>(op + (size_t)i * ROWSTRIDE) = acc;

        // Slide history window
        k4 = k3; k3 = k2; k2 = k1; k1 = ck;
        v4 = v3; v3 = v2; v2 = v1; v1 = cv;
    }
}

extern "C" void kernel_launch(void* const* d_in, const int* in_sizes, int n_in,
                              void* d_out, int out_size)
{
    const float* q = (const float*)d_in[0];
    const float* k = (const float*)d_in[1];
    const float* v = (const float*)d_in[2];
    const float* a = (const float*)d_in[3];
    const float* b = (const float*)d_in[4];
    float* out = (float*)d_out;

    gdr_pipe_kernel<<<NBLOCKS, THREADS>>>(q, k, v, a, b, out);
}